// round 15
// baseline (speedup 1.0000x reference)
#include <cuda_runtime.h>
#include <cuda_fp16.h>
#include <cstdint>
#include <math.h>

#define Tn   512
#define Bn   64
#define Hn   512
#define G4   2048
#define NOUT 128
#define Mtot (Tn * Bn)          // 32768
#define NCTA_LSTM 64

// ---------------- scratch ----------------
__device__ __half g_xwh[(size_t)2 * G4 * Mtot];      // xw_T[dir][n][m] fp16
__device__ float g_out1[(size_t)2 * Hn * Mtot];      // out1_T[dir][u][m] fp32 (attn input)
__device__ float g_logit[Tn * Bn];
__device__ float g_attnT[Tn * Bn];
__device__ float g_pooledT[Hn * Bn];
__device__ unsigned g_barv[64];
// h exchange buffers: [buf2][dir2][b64][k512] fp16
__device__ __half g_hbf[2 * 2 * 64 * 512];
// fp16 GEMM operands
__device__ __half g_xh[(size_t)Mtot * 1024];         // X [m][k]; layer0: k=256, layer1: k=1024
__device__ __half g_wh0[2 * G4 * 256];
__device__ __half g_wh1[2 * G4 * 1024];

__device__ __forceinline__ unsigned ldacq(const unsigned* p) {
    unsigned v;
    asm volatile("ld.acquire.gpu.global.b32 %0, [%1];" : "=r"(v) : "l"(p) : "memory");
    return v;
}
__device__ __forceinline__ void red_release(unsigned* p) {
    asm volatile("red.release.gpu.global.add.u32 [%0], %1;" :: "l"(p), "r"(1u) : "memory");
}
__device__ __forceinline__ float sigf(float x) {
    return 1.f / (1.f + __expf(-x));
}
__device__ __forceinline__ float tanhfast(float x) {
    return 1.f - 2.f / (1.f + __expf(2.f * x));
}

// ==================== mma.sync helpers ====================
__device__ __forceinline__ unsigned smem_u32(const void* p) {
    unsigned a;
    asm("{ .reg .u64 t; cvta.to.shared.u64 t, %1; cvt.u32.u64 %0, t; }" : "=r"(a) : "l"(p));
    return a;
}
__device__ __forceinline__ void ldsm4(unsigned& r0, unsigned& r1, unsigned& r2, unsigned& r3,
                                      unsigned addr) {
    asm volatile("ldmatrix.sync.aligned.m8n8.x4.shared.b16 {%0,%1,%2,%3}, [%4];"
                 : "=r"(r0), "=r"(r1), "=r"(r2), "=r"(r3) : "r"(addr));
}
__device__ __forceinline__ void ldsm2(unsigned& r0, unsigned& r1, unsigned addr) {
    asm volatile("ldmatrix.sync.aligned.m8n8.x2.shared.b16 {%0,%1}, [%2];"
                 : "=r"(r0), "=r"(r1) : "r"(addr));
}
__device__ __forceinline__ void mma16816h(float* c, const unsigned* a, unsigned b0, unsigned b1) {
    asm volatile(
        "mma.sync.aligned.m16n8k16.row.col.f32.f16.f16.f32 "
        "{%0,%1,%2,%3}, {%4,%5,%6,%7}, {%8,%9}, {%0,%1,%2,%3};"
        : "+f"(c[0]), "+f"(c[1]), "+f"(c[2]), "+f"(c[3])
        : "r"(a[0]), "r"(a[1]), "r"(a[2]), "r"(a[3]), "r"(b0), "r"(b1));
}
__device__ __forceinline__ void cpasync16(unsigned dst, const void* src) {
    asm volatile("cp.async.cg.shared.global [%0], [%1], 16;" :: "r"(dst), "l"(src));
}
__device__ __forceinline__ void cpasync_commit() {
    asm volatile("cp.async.commit_group;" ::: "memory");
}
__device__ __forceinline__ void cpasync_wait0() {
    asm volatile("cp.async.wait_group 0;" ::: "memory");
}
__device__ __forceinline__ void cpasync_wait1() {
    asm volatile("cp.async.wait_group 1;" ::: "memory");
}

// ==================== fp32 -> fp16 converter ====================
__global__ void convert_f16_kernel(const float* __restrict__ in,
                                   __half* __restrict__ out, int n) {
    int i = blockIdx.x * blockDim.x + threadIdx.x;
    for (; i < n; i += gridDim.x * blockDim.x)
        out[i] = __float2half_rn(in[i]);
}

// ==================== fp16 mma.sync GEMM, fp16 output (proven) ====================
#define GP      72
#define GTILE   (128 * GP * 2)          // 18432 B
#define GBUF    (2 * GTILE)             // W, X      (36864)
#define GEMM_SMEM (2 * GBUF)            // double buffer (73728)

__global__ __launch_bounds__(256, 2)
void mma_gemm_kernel(const __half* __restrict__ Wh, const __half* __restrict__ Xh,
                     const float* __restrict__ bias, __half* __restrict__ C, int K) {
    extern __shared__ char smem[];
    const unsigned sb = smem_u32(smem);
    const int tid = threadIdx.x;
    const int wid = tid >> 5, lane = tid & 31;
    const int wa = wid & 3;
    const int wb = wid >> 2;
    const int n0 = blockIdx.x * 128;
    const int m0 = blockIdx.y * 128;
    const int NC = K >> 6;

    const __half* gsrc[2] = {Wh + (size_t)n0 * K, Xh + (size_t)m0 * K};

    float acc[2][8][4];
#pragma unroll
    for (int i = 0; i < 2; i++)
#pragma unroll
        for (int j = 0; j < 8; j++)
#pragma unroll
            for (int q = 0; q < 4; q++) acc[i][j][q] = 0.f;

#pragma unroll
    for (int tgt = 0; tgt < 2; tgt++) {
#pragma unroll
        for (int i = 0; i < 4; i++) {
            int lin = tid + i * 256;
            int row = lin >> 3, unit = lin & 7;
            cpasync16(sb + tgt * GTILE + (row * GP + unit * 8) * 2,
                      gsrc[tgt] + (size_t)row * K + unit * 8);
        }
    }
    cpasync_commit();

    const int a_roff = (lane & 7) + ((lane >> 3) & 1) * 8;
    const int a_koff = ((lane >> 4) & 1) * 8;
    const int b_roff = (lane & 7) + ((lane >> 4) & 1) * 8;
    const int b_koff = ((lane >> 3) & 1) * 8;

#pragma unroll 1
    for (int c = 0; c < NC; c++) {
        cpasync_wait0();
        __syncthreads();
        if (c + 1 < NC) {
            const int kc = (c + 1) * 64;
            const unsigned bo = ((c + 1) & 1) * GBUF;
#pragma unroll
            for (int tgt = 0; tgt < 2; tgt++) {
#pragma unroll
                for (int i = 0; i < 4; i++) {
                    int lin = tid + i * 256;
                    int row = lin >> 3, unit = lin & 7;
                    cpasync16(sb + bo + tgt * GTILE + (row * GP + unit * 8) * 2,
                              gsrc[tgt] + (size_t)row * K + kc + unit * 8);
                }
            }
            cpasync_commit();
        }
        const unsigned cb = (c & 1) * GBUF;
#pragma unroll
        for (int ks = 0; ks < 4; ks++) {
            const int k0 = ks * 16;
            unsigned af[2][4], bf[4][4];
#pragma unroll
            for (int mf = 0; mf < 2; mf++) {
                int row = wa * 32 + mf * 16 + a_roff;
                ldsm4(af[mf][0], af[mf][1], af[mf][2], af[mf][3],
                      sb + cb + (row * GP + k0 + a_koff) * 2);
            }
#pragma unroll
            for (int nf = 0; nf < 4; nf++) {
                int row = wb * 64 + nf * 16 + b_roff;
                ldsm4(bf[nf][0], bf[nf][1], bf[nf][2], bf[nf][3],
                      sb + cb + GTILE + (row * GP + k0 + b_koff) * 2);
            }
#pragma unroll
            for (int mf = 0; mf < 2; mf++)
#pragma unroll
                for (int nf = 0; nf < 4; nf++)
#pragma unroll
                    for (int hf = 0; hf < 2; hf++)
                        mma16816h(acc[mf][nf * 2 + hf], af[mf],
                                  bf[nf][hf * 2], bf[nf][hf * 2 + 1]);
        }
        __syncthreads();
    }

    const int g = lane >> 2, tig = lane & 3;
#pragma unroll
    for (int mf = 0; mf < 2; mf++) {
        const int nr = n0 + wa * 32 + mf * 16 + g;
        const float bv0 = bias[nr];
        const float bv1 = bias[nr + 8];
#pragma unroll
        for (int j = 0; j < 8; j++) {
            const int mcol = m0 + wb * 64 + j * 8 + tig * 2;
            __half2 v0 = __floats2half2_rn(acc[mf][j][0] + bv0, acc[mf][j][1] + bv0);
            __half2 v1 = __floats2half2_rn(acc[mf][j][2] + bv1, acc[mf][j][3] + bv1);
            *(__half2*)&C[(size_t)nr * Mtot + mcol] = v0;
            *(__half2*)&C[(size_t)(nr + 8) * Mtot + mcol] = v1;
        }
    }
}

// ===================== init: zero h fp16 buffers + barrier counters =====================
__global__ void init_kernel() {
    int i = blockIdx.x * blockDim.x + threadIdx.x;
    if (i < 64) g_barv[i] = 0u;
    uint4* p = (uint4*)g_hbf;
    const int n = (2 * 2 * 64 * 512) / 8;
    for (int j = i; j < n; j += gridDim.x * blockDim.x)
        p[j] = make_uint4(0u, 0u, 0u, 0u);
}

// ===================== tensor-core persistent LSTM layer =====================
// CTA = (dir, 16 units), 512 threads, grid 64. A-tile = two stacked copies of
// the proven 32-row gate layout (rows [oct*32 + gate*8 + uu], unit = oct*8+uu).
// Warp wid: mh = wid&1 (unit octet), ws = wid>>1 (8-batch slice). Per-warp
// fragment pattern identical to R13. Halves h L2 broadcast + barrier width.
#define LAP 520
#define LSTM2_SMEM ((64 * LAP + 64 * LAP) * 2)   // 133120 B

template <int OUT_F16>
__global__ __launch_bounds__(512, 1)
void lstm_mma_kernel(const __half* __restrict__ xwT, const float* __restrict__ Whh,
                     float* __restrict__ outT, __half* __restrict__ outH) {
    extern __shared__ __half hbuf[];
    __half* sA = hbuf;                    // [64][520]
    __half* sB = sA + 64 * LAP;           // [64][520]

    const int tid = threadIdx.x;
    const int wid = tid >> 5, lane = tid & 31;
    const int dir = blockIdx.x >> 5;
    const int u0 = (blockIdx.x & 31) << 4;

    // load Whh slice: tile row r = oct*32 + gate*8 + uu  -> unit u0 + oct*8 + uu
    for (int i = tid; i < 64 * 512; i += 512) {
        int r = i >> 9, k = i & 511;
        int oct = r >> 5, gate = (r >> 3) & 3, uu = r & 7;
        float w = Whh[((size_t)dir * G4 + gate * Hn + u0 + oct * 8 + uu) * Hn + k];
        sA[r * LAP + k] = __float2half_rn(w);
    }

    const unsigned aA = smem_u32(sA);
    const unsigned aB = smem_u32(sB);

    const int a_roff = (lane & 7) + ((lane >> 3) & 1) * 8;
    const int a_koff = ((lane >> 4) & 1) * 8;
    const int b_roff = lane & 7;
    const int b_koff = ((lane >> 3) & 1) * 8;

    const int mh = wid & 1;              // unit octet
    const int ws = wid >> 1;             // batch slice (8 batches)
    const int g = lane >> 2;             // unit-local within octet
    const int tig = lane & 3;
    const int bb = ws * 8 + tig * 2;     // first of this thread's 2 batches
    const int uu = u0 + mh * 8 + g;      // this thread's unit

    float c0 = 0.f, c1 = 0.f;
    unsigned* ctr = &g_barv[dir * 32];
    const size_t xrow = (size_t)dir * G4 + uu;
    const unsigned aAw = aA + (mh * 32 * LAP) * 2;   // this warp's A octet base

#pragma unroll 1
    for (int s = 0; s < Tn; s++) {
        const int t = dir ? (Tn - 1 - s) : s;
        const size_t mo = (size_t)t * Bn + bb;

        // stage h(s) fp16 into smem [b][k], two k-half cp.async groups
        {
            const __half* gh = g_hbf + (((size_t)(s & 1) * 2 + dir) << 15);
#pragma unroll
            for (int it = 0; it < 4; it++) {
                int i = tid + it * 512;
                int b = i >> 5, j = (i & 31) * 8;
                cpasync16(aB + (b * LAP + j) * 2, gh + b * 512 + j);
            }
            cpasync_commit();
#pragma unroll
            for (int it = 0; it < 4; it++) {
                int i = tid + it * 512;
                int b = i >> 5, j = 256 + (i & 31) * 8;
                cpasync16(aB + (b * LAP + j) * 2, gh + b * 512 + j);
            }
            cpasync_commit();
        }

        // xw for all 4 gates — overlaps cp.async flight
        float2 xwi = __half22float2(__ldg((const __half2*)&xwT[(xrow + 0 * Hn) * Mtot + mo]));
        float2 xwf = __half22float2(__ldg((const __half2*)&xwT[(xrow + 1 * Hn) * Mtot + mo]));
        float2 xwg = __half22float2(__ldg((const __half2*)&xwT[(xrow + 2 * Hn) * Mtot + mo]));
        float2 xwo = __half22float2(__ldg((const __half2*)&xwT[(xrow + 3 * Hn) * Mtot + mo]));

        float acc0[4] = {0.f, 0.f, 0.f, 0.f};  // gates 0(i),1(f) of unit uu
        float acc1[4] = {0.f, 0.f, 0.f, 0.f};  // gates 2(g),3(o)

        cpasync_wait1();
        __syncthreads();
#pragma unroll 8
        for (int ks = 0; ks < 16; ks++) {
            const int k0 = ks * 16;
            unsigned ah0[4], ah1[4];
            unsigned ad = aAw + ((a_roff) * LAP + k0 + a_koff) * 2;
            ldsm4(ah0[0], ah0[1], ah0[2], ah0[3], ad);
            ldsm4(ah1[0], ah1[1], ah1[2], ah1[3], ad + 16 * LAP * 2);
            unsigned b0, b1;
            ldsm2(b0, b1, aB + ((ws * 8 + b_roff) * LAP + k0 + b_koff) * 2);
            mma16816h(acc0, ah0, b0, b1);
            mma16816h(acc1, ah1, b0, b1);
        }
        cpasync_wait0();
        __syncthreads();
#pragma unroll 8
        for (int ks = 16; ks < 32; ks++) {
            const int k0 = ks * 16;
            unsigned ah0[4], ah1[4];
            unsigned ad = aAw + ((a_roff) * LAP + k0 + a_koff) * 2;
            ldsm4(ah0[0], ah0[1], ah0[2], ah0[3], ad);
            ldsm4(ah1[0], ah1[1], ah1[2], ah1[3], ad + 16 * LAP * 2);
            unsigned b0, b1;
            ldsm2(b0, b1, aB + ((ws * 8 + b_roff) * LAP + k0 + b_koff) * 2);
            mma16816h(acc0, ah0, b0, b1);
            mma16816h(acc1, ah1, b0, b1);
        }

        // pointwise in registers
        float i0 = sigf(acc0[0] + xwi.x);
        float i1 = sigf(acc0[1] + xwi.y);
        float f0 = sigf(acc0[2] + xwf.x);
        float f1 = sigf(acc0[3] + xwf.y);
        float gg0 = tanhfast(acc1[0] + xwg.x);
        float gg1 = tanhfast(acc1[1] + xwg.y);
        float o0 = sigf(acc1[2] + xwo.x);
        float o1 = sigf(acc1[3] + xwo.y);

        c0 = fminf(fmaxf(f0 * c0 + i0 * gg0, -100.f), 100.f);
        c1 = fminf(fmaxf(f1 * c1 + i1 * gg1, -100.f), 100.f);
        float h0 = o0 * tanhfast(c0);
        float h1 = o1 * tanhfast(c1);
        __half h0h = __float2half_rn(h0);
        __half h1h = __float2half_rn(h1);

        // fp16 h for next step FIRST (peers wait on this)
        {
            __half* wh = g_hbf + (((size_t)((s + 1) & 1) * 2 + dir) << 15);
            wh[(size_t)bb * 512 + uu] = h0h;
            wh[(size_t)(bb + 1) * 512 + uu] = h1h;
        }

        if (s < Tn - 1) {
            __syncthreads();                 // all h stores issued
            if (tid == 0) red_release(ctr);  // arrive (orders prior writes)
            // peer-independent layer-output store overlaps barrier drain
            if (OUT_F16) {
                outH[mo * 1024 + dir * Hn + uu] = h0h;
                outH[(mo + 1) * 1024 + dir * Hn + uu] = h1h;
            } else {
                *(float2*)&outT[((size_t)dir * Hn + uu) * Mtot + mo] = make_float2(h0, h1);
            }
            if (tid == 0) {
                unsigned target = 32u * (unsigned)(s + 1);
                while (ldacq(ctr) < target) {}
            }
            __syncthreads();
        } else {
            if (OUT_F16) {
                outH[mo * 1024 + dir * Hn + uu] = h0h;
                outH[(mo + 1) * 1024 + dir * Hn + uu] = h1h;
            } else {
                *(float2*)&outT[((size_t)dir * Hn + uu) * Mtot + mo] = make_float2(h0, h1);
            }
        }
    }
}

// ===================== attention logits =====================
__global__ __launch_bounds__(512)
void attn_logit_kernel(const float* __restrict__ h1T, const float* __restrict__ Wa,
                       const float* __restrict__ ba, float* __restrict__ logit) {
    __shared__ float sWa[Hn];
    __shared__ float red[8][64];
    const int t = blockIdx.x;
    const int ug = threadIdx.x >> 6, b = threadIdx.x & 63;
    sWa[threadIdx.x] = Wa[threadIdx.x];
    __syncthreads();

    float acc = 0.f;
    const size_t moff = (size_t)t * Bn + b;
#pragma unroll 4
    for (int uu = 0; uu < 64; uu++) {
        int u = ug * 64 + uu;
        float hf = h1T[(size_t)u * Mtot + moff];
        float hb = h1T[((size_t)Hn + u) * Mtot + moff];
        acc += (hf + hb) * sWa[u];
    }
    red[ug][b] = acc;
    __syncthreads();
    if (ug == 0) {
        float s = ba[0];
#pragma unroll
        for (int g = 0; g < 8; g++) s += red[g][b];
        logit[t * Bn + b] = s;
    }
}

// ===================== softmax over t (CTA per b) =====================
__global__ __launch_bounds__(512)
void softmax_kernel(const float* __restrict__ logit, float* __restrict__ outp,
                    float* __restrict__ aT) {
    __shared__ float red[Tn];
    const int b = blockIdx.x, t = threadIdx.x;
    float v = logit[t * Bn + b];
    red[t] = v; __syncthreads();
    for (int st = 256; st > 0; st >>= 1) {
        if (t < st) red[t] = fmaxf(red[t], red[t + st]);
        __syncthreads();
    }
    float m = red[0]; __syncthreads();
    float e = expf(v - m);
    red[t] = e; __syncthreads();
    for (int st = 256; st > 0; st >>= 1) {
        if (t < st) red[t] += red[t + st];
        __syncthreads();
    }
    float a = e / red[0];
    outp[Bn * NOUT + b * Tn + t] = a;
    aT[t * Bn + b] = a;
}

// ===================== attention pooling (CTA per u, 512 threads) =====================
__global__ __launch_bounds__(512)
void pool_kernel(const float* __restrict__ h1T, const float* __restrict__ aT,
                 float* __restrict__ pooledT) {
    __shared__ float red[8][64];
    const int u = blockIdx.x;
    const int tt = threadIdx.x >> 6, b = threadIdx.x & 63;
    const float* hf = h1T + (size_t)u * Mtot;
    const float* hb = h1T + ((size_t)Hn + u) * Mtot;
    float acc = 0.f;
#pragma unroll 4
    for (int t = tt * 64; t < tt * 64 + 64; t++)
        acc += (hf[t * Bn + b] + hb[t * Bn + b]) * aT[t * Bn + b];
    red[tt][b] = acc;
    __syncthreads();
    if (tt == 0) {
        float s = 0.f;
#pragma unroll
        for (int g = 0; g < 8; g++) s += red[g][b];
        pooledT[u * Bn + b] = s;
    }
}

// ===================== output head (CTA per b) =====================
__global__ __launch_bounds__(128)
void pred_kernel(const float* __restrict__ pooledT, const float* __restrict__ Wo,
                 const float* __restrict__ bo, float* __restrict__ outp) {
    __shared__ float sp[Hn];
    const int b = blockIdx.x, o = threadIdx.x;
    for (int u = o; u < Hn; u += 128) sp[u] = pooledT[u * Bn + b];
    __syncthreads();
    float s = bo[o];
    const float* wp = Wo + (size_t)o * Hn;
#pragma unroll 4
    for (int u = 0; u < Hn; u++) s += sp[u] * wp[u];
    outp[b * NOUT + o] = s;
}

// ===================== launch =====================
extern "C" void kernel_launch(void* const* d_in, const int* in_sizes, int n_in,
                              void* d_out, int out_size) {
    (void)in_sizes; (void)n_in; (void)out_size;
    const float* input = (const float*)d_in[0];
    const float* Wih0  = (const float*)d_in[1];
    const float* Whh0  = (const float*)d_in[2];
    const float* b0    = (const float*)d_in[3];
    const float* Wih1  = (const float*)d_in[4];
    const float* Whh1  = (const float*)d_in[5];
    const float* b1    = (const float*)d_in[6];
    const float* Wa    = (const float*)d_in[7];
    const float* ba    = (const float*)d_in[8];
    const float* Wo    = (const float*)d_in[9];
    const float* bo    = (const float*)d_in[10];
    float* outp = (float*)d_out;

    float *out1, *logit, *aT, *pooledT;
    __half *xwh, *xh, *wh0, *wh1;
    cudaGetSymbolAddress((void**)&xwh, g_xwh);
    cudaGetSymbolAddress((void**)&out1, g_out1);
    cudaGetSymbolAddress((void**)&logit, g_logit);
    cudaGetSymbolAddress((void**)&aT, g_attnT);
    cudaGetSymbolAddress((void**)&pooledT, g_pooledT);
    cudaGetSymbolAddress((void**)&xh, g_xh);
    cudaGetSymbolAddress((void**)&wh0, g_wh0);
    cudaGetSymbolAddress((void**)&wh1, g_wh1);

    cudaFuncSetAttribute(lstm_mma_kernel<0>, cudaFuncAttributeMaxDynamicSharedMemorySize,
                         LSTM2_SMEM);
    cudaFuncSetAttribute(lstm_mma_kernel<1>, cudaFuncAttributeMaxDynamicSharedMemorySize,
                         LSTM2_SMEM);
    cudaFuncSetAttribute(mma_gemm_kernel, cudaFuncAttributeMaxDynamicSharedMemorySize,
                         GEMM_SMEM);

    dim3 mgrid(32, 256);   // 32 n-tiles (4096/128), 256 m-tiles

    // ---- layer 0 ----
    convert_f16_kernel<<<1024, 256>>>(Wih0, wh0, 2 * G4 * 256);
    convert_f16_kernel<<<2048, 256>>>(input, xh, Mtot * 256);
    mma_gemm_kernel<<<mgrid, 256, GEMM_SMEM>>>(wh0, xh, b0, xwh, 256);
    convert_f16_kernel<<<2048, 256>>>(Wih1, wh1, 2 * G4 * 1024);
    init_kernel<<<64, 256>>>();
    // layer-0 LSTM writes its output straight into xh as [m][dir*512+u] fp16
    lstm_mma_kernel<1><<<NCTA_LSTM, 512, LSTM2_SMEM>>>(xwh, Whh0, nullptr, xh);

    // ---- layer 1 ----
    mma_gemm_kernel<<<mgrid, 256, GEMM_SMEM>>>(wh1, xh, b1, xwh, 1024);
    init_kernel<<<64, 256>>>();
    lstm_mma_kernel<0><<<NCTA_LSTM, 512, LSTM2_SMEM>>>(xwh, Whh1, out1, nullptr);

    // ---- attention + head ----
    attn_logit_kernel<<<Tn, 512>>>(out1, Wa, ba, logit);
    softmax_kernel<<<Bn, Tn>>>(logit, outp, aT);
    pool_kernel<<<Hn, 512>>>(out1, aT, pooledT);
    pred_kernel<<<Bn, NOUT>>>(pooledT, Wo, bo, outp);
}

// round 16
// speedup vs baseline: 1.1581x; 1.1581x over previous
#include <cuda_runtime.h>
#include <cuda_fp16.h>
#include <cstdint>
#include <math.h>

#define Tn   512
#define Bn   64
#define Hn   512
#define G4   2048
#define NOUT 128
#define Mtot (Tn * Bn)          // 32768
#define NCTA_LSTM 128

// ---------------- scratch ----------------
__device__ __half g_xwh[(size_t)2 * G4 * Mtot];      // xw_T[dir][n][m] fp16
__device__ __half g_out1h[(size_t)2 * Hn * Mtot];    // out1_T[dir][u][m] fp16 (attn input)
__device__ float g_logit[Tn * Bn];
__device__ float g_attnT[Tn * Bn];
__device__ float g_pooledT[Hn * Bn];
__device__ unsigned g_barv[64];
// h exchange buffers: [buf2][dir2][b64][k512] fp16
__device__ __half g_hbf[2 * 2 * 64 * 512];
// fp16 GEMM operands
__device__ __half g_xh[(size_t)Mtot * 1024];         // X [m][k]; layer0: k=256, layer1: k=1024
__device__ __half g_wh0[2 * G4 * 256];
__device__ __half g_wh1[2 * G4 * 1024];

__device__ __forceinline__ unsigned ldacq(const unsigned* p) {
    unsigned v;
    asm volatile("ld.acquire.gpu.global.b32 %0, [%1];" : "=r"(v) : "l"(p) : "memory");
    return v;
}
__device__ __forceinline__ void red_release(unsigned* p) {
    asm volatile("red.release.gpu.global.add.u32 [%0], %1;" :: "l"(p), "r"(1u) : "memory");
}
__device__ __forceinline__ float sigf(float x) {
    return 1.f / (1.f + __expf(-x));
}
__device__ __forceinline__ float tanhfast(float x) {
    return 1.f - 2.f / (1.f + __expf(2.f * x));
}

// ==================== mma.sync helpers ====================
__device__ __forceinline__ unsigned smem_u32(const void* p) {
    unsigned a;
    asm("{ .reg .u64 t; cvta.to.shared.u64 t, %1; cvt.u32.u64 %0, t; }" : "=r"(a) : "l"(p));
    return a;
}
__device__ __forceinline__ void ldsm4(unsigned& r0, unsigned& r1, unsigned& r2, unsigned& r3,
                                      unsigned addr) {
    asm volatile("ldmatrix.sync.aligned.m8n8.x4.shared.b16 {%0,%1,%2,%3}, [%4];"
                 : "=r"(r0), "=r"(r1), "=r"(r2), "=r"(r3) : "r"(addr));
}
__device__ __forceinline__ void ldsm2(unsigned& r0, unsigned& r1, unsigned addr) {
    asm volatile("ldmatrix.sync.aligned.m8n8.x2.shared.b16 {%0,%1}, [%2];"
                 : "=r"(r0), "=r"(r1) : "r"(addr));
}
__device__ __forceinline__ void mma16816h(float* c, const unsigned* a, unsigned b0, unsigned b1) {
    asm volatile(
        "mma.sync.aligned.m16n8k16.row.col.f32.f16.f16.f32 "
        "{%0,%1,%2,%3}, {%4,%5,%6,%7}, {%8,%9}, {%0,%1,%2,%3};"
        : "+f"(c[0]), "+f"(c[1]), "+f"(c[2]), "+f"(c[3])
        : "r"(a[0]), "r"(a[1]), "r"(a[2]), "r"(a[3]), "r"(b0), "r"(b1));
}
__device__ __forceinline__ void cpasync16(unsigned dst, const void* src) {
    asm volatile("cp.async.cg.shared.global [%0], [%1], 16;" :: "r"(dst), "l"(src));
}
__device__ __forceinline__ void cpasync_commit() {
    asm volatile("cp.async.commit_group;" ::: "memory");
}
__device__ __forceinline__ void cpasync_wait0() {
    asm volatile("cp.async.wait_group 0;" ::: "memory");
}
__device__ __forceinline__ void cpasync_wait1() {
    asm volatile("cp.async.wait_group 1;" ::: "memory");
}

// ==================== fp32 -> fp16 converter ====================
__global__ void convert_f16_kernel(const float* __restrict__ in,
                                   __half* __restrict__ out, int n) {
    int i = blockIdx.x * blockDim.x + threadIdx.x;
    for (; i < n; i += gridDim.x * blockDim.x)
        out[i] = __float2half_rn(in[i]);
}

// ==================== fp16 mma.sync GEMM, fp16 output (proven) ====================
#define GP      72
#define GTILE   (128 * GP * 2)          // 18432 B
#define GBUF    (2 * GTILE)             // W, X      (36864)
#define GEMM_SMEM (2 * GBUF)            // double buffer (73728)

__global__ __launch_bounds__(256, 2)
void mma_gemm_kernel(const __half* __restrict__ Wh, const __half* __restrict__ Xh,
                     const float* __restrict__ bias, __half* __restrict__ C, int K) {
    extern __shared__ char smem[];
    const unsigned sb = smem_u32(smem);
    const int tid = threadIdx.x;
    const int wid = tid >> 5, lane = tid & 31;
    const int wa = wid & 3;
    const int wb = wid >> 2;
    const int n0 = blockIdx.x * 128;
    const int m0 = blockIdx.y * 128;
    const int NC = K >> 6;

    const __half* gsrc[2] = {Wh + (size_t)n0 * K, Xh + (size_t)m0 * K};

    float acc[2][8][4];
#pragma unroll
    for (int i = 0; i < 2; i++)
#pragma unroll
        for (int j = 0; j < 8; j++)
#pragma unroll
            for (int q = 0; q < 4; q++) acc[i][j][q] = 0.f;

#pragma unroll
    for (int tgt = 0; tgt < 2; tgt++) {
#pragma unroll
        for (int i = 0; i < 4; i++) {
            int lin = tid + i * 256;
            int row = lin >> 3, unit = lin & 7;
            cpasync16(sb + tgt * GTILE + (row * GP + unit * 8) * 2,
                      gsrc[tgt] + (size_t)row * K + unit * 8);
        }
    }
    cpasync_commit();

    const int a_roff = (lane & 7) + ((lane >> 3) & 1) * 8;
    const int a_koff = ((lane >> 4) & 1) * 8;
    const int b_roff = (lane & 7) + ((lane >> 4) & 1) * 8;
    const int b_koff = ((lane >> 3) & 1) * 8;

#pragma unroll 1
    for (int c = 0; c < NC; c++) {
        cpasync_wait0();
        __syncthreads();
        if (c + 1 < NC) {
            const int kc = (c + 1) * 64;
            const unsigned bo = ((c + 1) & 1) * GBUF;
#pragma unroll
            for (int tgt = 0; tgt < 2; tgt++) {
#pragma unroll
                for (int i = 0; i < 4; i++) {
                    int lin = tid + i * 256;
                    int row = lin >> 3, unit = lin & 7;
                    cpasync16(sb + bo + tgt * GTILE + (row * GP + unit * 8) * 2,
                              gsrc[tgt] + (size_t)row * K + kc + unit * 8);
                }
            }
            cpasync_commit();
        }
        const unsigned cb = (c & 1) * GBUF;
#pragma unroll
        for (int ks = 0; ks < 4; ks++) {
            const int k0 = ks * 16;
            unsigned af[2][4], bf[4][4];
#pragma unroll
            for (int mf = 0; mf < 2; mf++) {
                int row = wa * 32 + mf * 16 + a_roff;
                ldsm4(af[mf][0], af[mf][1], af[mf][2], af[mf][3],
                      sb + cb + (row * GP + k0 + a_koff) * 2);
            }
#pragma unroll
            for (int nf = 0; nf < 4; nf++) {
                int row = wb * 64 + nf * 16 + b_roff;
                ldsm4(bf[nf][0], bf[nf][1], bf[nf][2], bf[nf][3],
                      sb + cb + GTILE + (row * GP + k0 + b_koff) * 2);
            }
#pragma unroll
            for (int mf = 0; mf < 2; mf++)
#pragma unroll
                for (int nf = 0; nf < 4; nf++)
#pragma unroll
                    for (int hf = 0; hf < 2; hf++)
                        mma16816h(acc[mf][nf * 2 + hf], af[mf],
                                  bf[nf][hf * 2], bf[nf][hf * 2 + 1]);
        }
        __syncthreads();
    }

    const int g = lane >> 2, tig = lane & 3;
#pragma unroll
    for (int mf = 0; mf < 2; mf++) {
        const int nr = n0 + wa * 32 + mf * 16 + g;
        const float bv0 = bias[nr];
        const float bv1 = bias[nr + 8];
#pragma unroll
        for (int j = 0; j < 8; j++) {
            const int mcol = m0 + wb * 64 + j * 8 + tig * 2;
            __half2 v0 = __floats2half2_rn(acc[mf][j][0] + bv0, acc[mf][j][1] + bv0);
            __half2 v1 = __floats2half2_rn(acc[mf][j][2] + bv1, acc[mf][j][3] + bv1);
            *(__half2*)&C[(size_t)nr * Mtot + mcol] = v0;
            *(__half2*)&C[(size_t)(nr + 8) * Mtot + mcol] = v1;
        }
    }
}

// ===================== init: zero h fp16 buffers + barrier counters =====================
__global__ void init_kernel() {
    int i = blockIdx.x * blockDim.x + threadIdx.x;
    if (i < 64) g_barv[i] = 0u;
    uint4* p = (uint4*)g_hbf;
    const int n = (2 * 2 * 64 * 512) / 8;
    for (int j = i; j < n; j += gridDim.x * blockDim.x)
        p[j] = make_uint4(0u, 0u, 0u, 0u);
}

// ===================== tensor-core persistent LSTM layer (R13 config) =====================
// OUT_F16=1: store h as fp16 [m][dir*512+u] into outH (layer-1 GEMM input layout).
// OUT_F16=0: store h as fp16 [dir*512+u][m] into outT (attention input layout).
#define LAP 520
#define LSTM2_SMEM ((32 * LAP + 64 * LAP) * 2)   // 99840 B

template <int OUT_F16>
__global__ __launch_bounds__(256, 1)
void lstm_mma_kernel(const __half* __restrict__ xwT, const float* __restrict__ Whh,
                     __half* __restrict__ outT, __half* __restrict__ outH) {
    extern __shared__ __half hbuf[];
    __half* sAhi = hbuf;                    // [32][520]
    __half* sB   = sAhi + 32 * LAP;         // [64][520]

    const int tid = threadIdx.x;
    const int wid = tid >> 5, lane = tid & 31;
    const int dir = blockIdx.x >> 6;
    const int u0 = (blockIdx.x & 63) << 3;

    for (int i = tid; i < 32 * 512; i += 256) {
        int r = i >> 9, k = i & 511;
        int gate = r >> 3, ul = r & 7;
        float w = Whh[((size_t)dir * G4 + gate * Hn + u0 + ul) * Hn + k];
        sAhi[r * LAP + k] = __float2half_rn(w);
    }

    const unsigned aAhi = smem_u32(sAhi);
    const unsigned aB   = smem_u32(sB);

    const int a_roff = (lane & 7) + ((lane >> 3) & 1) * 8;
    const int a_koff = ((lane >> 4) & 1) * 8;
    const int b_roff = lane & 7;
    const int b_koff = ((lane >> 3) & 1) * 8;

    const int g = lane >> 2;             // unit-local; acc rows {g,g+8,g+16,g+24}
    const int tig = lane & 3;
    const int bb = wid * 8 + tig * 2;    // first of this thread's 2 batches

    float c0 = 0.f, c1 = 0.f;
    unsigned* ctr = &g_barv[dir * 32];
    const size_t xrow = (size_t)dir * G4 + u0 + g;

#pragma unroll 1
    for (int s = 0; s < Tn; s++) {
        const int t = dir ? (Tn - 1 - s) : s;
        const size_t mo = (size_t)t * Bn + bb;

        // stage h(s) fp16 into smem [b][k], two k-half cp.async groups
        {
            const __half* gh = g_hbf + (((size_t)(s & 1) * 2 + dir) << 15);
#pragma unroll
            for (int it = 0; it < 8; it++) {
                int i = tid + it * 256;
                int b = i >> 5, j = (i & 31) * 8;
                cpasync16(aB + (b * LAP + j) * 2, gh + b * 512 + j);
            }
            cpasync_commit();
#pragma unroll
            for (int it = 0; it < 8; it++) {
                int i = tid + it * 256;
                int b = i >> 5, j = 256 + (i & 31) * 8;
                cpasync16(aB + (b * LAP + j) * 2, gh + b * 512 + j);
            }
            cpasync_commit();
        }

        // xw for all 4 gates (fp16 pair -> fp32) — overlaps cp.async flight
        float2 xwi = __half22float2(__ldg((const __half2*)&xwT[(xrow + 0 * Hn) * Mtot + mo]));
        float2 xwf = __half22float2(__ldg((const __half2*)&xwT[(xrow + 1 * Hn) * Mtot + mo]));
        float2 xwg = __half22float2(__ldg((const __half2*)&xwT[(xrow + 2 * Hn) * Mtot + mo]));
        float2 xwo = __half22float2(__ldg((const __half2*)&xwT[(xrow + 3 * Hn) * Mtot + mo]));

        float acc0[4] = {0.f, 0.f, 0.f, 0.f};  // rows g(i), g+8(f)
        float acc1[4] = {0.f, 0.f, 0.f, 0.f};  // rows 16+g(g), 24+g(o)

        // first k-half ready -> compute ks 0..15 while second half lands
        cpasync_wait1();
        __syncthreads();
#pragma unroll 8
        for (int ks = 0; ks < 16; ks++) {
            const int k0 = ks * 16;
            unsigned ah0[4], ah1[4];
            unsigned ad = aAhi + ((a_roff) * LAP + k0 + a_koff) * 2;
            ldsm4(ah0[0], ah0[1], ah0[2], ah0[3], ad);
            ldsm4(ah1[0], ah1[1], ah1[2], ah1[3], ad + 16 * LAP * 2);
            unsigned b0, b1;
            ldsm2(b0, b1, aB + ((wid * 8 + b_roff) * LAP + k0 + b_koff) * 2);
            mma16816h(acc0, ah0, b0, b1);
            mma16816h(acc1, ah1, b0, b1);
        }
        cpasync_wait0();
        __syncthreads();
#pragma unroll 8
        for (int ks = 16; ks < 32; ks++) {
            const int k0 = ks * 16;
            unsigned ah0[4], ah1[4];
            unsigned ad = aAhi + ((a_roff) * LAP + k0 + a_koff) * 2;
            ldsm4(ah0[0], ah0[1], ah0[2], ah0[3], ad);
            ldsm4(ah1[0], ah1[1], ah1[2], ah1[3], ad + 16 * LAP * 2);
            unsigned b0, b1;
            ldsm2(b0, b1, aB + ((wid * 8 + b_roff) * LAP + k0 + b_koff) * 2);
            mma16816h(acc0, ah0, b0, b1);
            mma16816h(acc1, ah1, b0, b1);
        }

        // pointwise in registers
        float i0 = sigf(acc0[0] + xwi.x);
        float i1 = sigf(acc0[1] + xwi.y);
        float f0 = sigf(acc0[2] + xwf.x);
        float f1 = sigf(acc0[3] + xwf.y);
        float gg0 = tanhfast(acc1[0] + xwg.x);
        float gg1 = tanhfast(acc1[1] + xwg.y);
        float o0 = sigf(acc1[2] + xwo.x);
        float o1 = sigf(acc1[3] + xwo.y);

        c0 = fminf(fmaxf(f0 * c0 + i0 * gg0, -100.f), 100.f);
        c1 = fminf(fmaxf(f1 * c1 + i1 * gg1, -100.f), 100.f);
        float h0 = o0 * tanhfast(c0);
        float h1 = o1 * tanhfast(c1);
        __half h0h = __float2half_rn(h0);
        __half h1h = __float2half_rn(h1);

        // fp16 h for next step FIRST (peers wait on this)
        {
            __half* wh = g_hbf + (((size_t)((s + 1) & 1) * 2 + dir) << 15);
            wh[(size_t)bb * 512 + u0 + g] = h0h;
            wh[(size_t)(bb + 1) * 512 + u0 + g] = h1h;
        }

        if (s < Tn - 1) {
            __syncthreads();                 // all h stores issued
            if (tid == 0) red_release(ctr);  // arrive (orders prior writes)
            // peer-independent layer-output store overlaps barrier drain
            if (OUT_F16) {
                outH[mo * 1024 + dir * Hn + u0 + g] = h0h;
                outH[(mo + 1) * 1024 + dir * Hn + u0 + g] = h1h;
            } else {
                *(__half2*)&outT[((size_t)dir * Hn + u0 + g) * Mtot + mo] =
                    __halves2half2(h0h, h1h);
            }
            if (tid == 0) {
                unsigned target = 64u * (unsigned)(s + 1);
                while (ldacq(ctr) < target) {}
            }
            __syncthreads();
        } else {
            if (OUT_F16) {
                outH[mo * 1024 + dir * Hn + u0 + g] = h0h;
                outH[(mo + 1) * 1024 + dir * Hn + u0 + g] = h1h;
            } else {
                *(__half2*)&outT[((size_t)dir * Hn + u0 + g) * Mtot + mo] =
                    __halves2half2(h0h, h1h);
            }
        }
    }
}

// ===================== attention logits (fp16 input) =====================
__global__ __launch_bounds__(512)
void attn_logit_kernel(const __half* __restrict__ h1T, const float* __restrict__ Wa,
                       const float* __restrict__ ba, float* __restrict__ logit) {
    __shared__ float sWa[Hn];
    __shared__ float red[8][64];
    const int t = blockIdx.x;
    const int ug = threadIdx.x >> 6, b = threadIdx.x & 63;
    sWa[threadIdx.x] = Wa[threadIdx.x];
    __syncthreads();

    float acc = 0.f;
    const size_t moff = (size_t)t * Bn + b;
#pragma unroll 4
    for (int uu = 0; uu < 64; uu++) {
        int u = ug * 64 + uu;
        float hf = __half2float(h1T[(size_t)u * Mtot + moff]);
        float hb = __half2float(h1T[((size_t)Hn + u) * Mtot + moff]);
        acc += (hf + hb) * sWa[u];
    }
    red[ug][b] = acc;
    __syncthreads();
    if (ug == 0) {
        float s = ba[0];
#pragma unroll
        for (int g = 0; g < 8; g++) s += red[g][b];
        logit[t * Bn + b] = s;
    }
}

// ===================== softmax over t (CTA per b) =====================
__global__ __launch_bounds__(512)
void softmax_kernel(const float* __restrict__ logit, float* __restrict__ outp,
                    float* __restrict__ aT) {
    __shared__ float red[Tn];
    const int b = blockIdx.x, t = threadIdx.x;
    float v = logit[t * Bn + b];
    red[t] = v; __syncthreads();
    for (int st = 256; st > 0; st >>= 1) {
        if (t < st) red[t] = fmaxf(red[t], red[t + st]);
        __syncthreads();
    }
    float m = red[0]; __syncthreads();
    float e = expf(v - m);
    red[t] = e; __syncthreads();
    for (int st = 256; st > 0; st >>= 1) {
        if (t < st) red[t] += red[t + st];
        __syncthreads();
    }
    float a = e / red[0];
    outp[Bn * NOUT + b * Tn + t] = a;
    aT[t * Bn + b] = a;
}

// ===================== attention pooling (CTA per u, 512 threads, fp16 input) ==========
__global__ __launch_bounds__(512)
void pool_kernel(const __half* __restrict__ h1T, const float* __restrict__ aT,
                 float* __restrict__ pooledT) {
    __shared__ float red[8][64];
    const int u = blockIdx.x;
    const int tt = threadIdx.x >> 6, b = threadIdx.x & 63;
    const __half* hf = h1T + (size_t)u * Mtot;
    const __half* hb = h1T + ((size_t)Hn + u) * Mtot;
    float acc = 0.f;
#pragma unroll 4
    for (int t = tt * 64; t < tt * 64 + 64; t++)
        acc += (__half2float(hf[t * Bn + b]) + __half2float(hb[t * Bn + b])) * aT[t * Bn + b];
    red[tt][b] = acc;
    __syncthreads();
    if (tt == 0) {
        float s = 0.f;
#pragma unroll
        for (int g = 0; g < 8; g++) s += red[g][b];
        pooledT[u * Bn + b] = s;
    }
}

// ===================== output head (CTA per b) =====================
__global__ __launch_bounds__(128)
void pred_kernel(const float* __restrict__ pooledT, const float* __restrict__ Wo,
                 const float* __restrict__ bo, float* __restrict__ outp) {
    __shared__ float sp[Hn];
    const int b = blockIdx.x, o = threadIdx.x;
    for (int u = o; u < Hn; u += 128) sp[u] = pooledT[u * Bn + b];
    __syncthreads();
    float s = bo[o];
    const float* wp = Wo + (size_t)o * Hn;
#pragma unroll 4
    for (int u = 0; u < Hn; u++) s += sp[u] * wp[u];
    outp[b * NOUT + o] = s;
}

// ===================== launch =====================
extern "C" void kernel_launch(void* const* d_in, const int* in_sizes, int n_in,
                              void* d_out, int out_size) {
    (void)in_sizes; (void)n_in; (void)out_size;
    const float* input = (const float*)d_in[0];
    const float* Wih0  = (const float*)d_in[1];
    const float* Whh0  = (const float*)d_in[2];
    const float* b0    = (const float*)d_in[3];
    const float* Wih1  = (const float*)d_in[4];
    const float* Whh1  = (const float*)d_in[5];
    const float* b1    = (const float*)d_in[6];
    const float* Wa    = (const float*)d_in[7];
    const float* ba    = (const float*)d_in[8];
    const float* Wo    = (const float*)d_in[9];
    const float* bo    = (const float*)d_in[10];
    float* outp = (float*)d_out;

    float *logit, *aT, *pooledT;
    __half *xwh, *xh, *wh0, *wh1, *out1h;
    cudaGetSymbolAddress((void**)&xwh, g_xwh);
    cudaGetSymbolAddress((void**)&out1h, g_out1h);
    cudaGetSymbolAddress((void**)&logit, g_logit);
    cudaGetSymbolAddress((void**)&aT, g_attnT);
    cudaGetSymbolAddress((void**)&pooledT, g_pooledT);
    cudaGetSymbolAddress((void**)&xh, g_xh);
    cudaGetSymbolAddress((void**)&wh0, g_wh0);
    cudaGetSymbolAddress((void**)&wh1, g_wh1);

    cudaFuncSetAttribute(lstm_mma_kernel<0>, cudaFuncAttributeMaxDynamicSharedMemorySize,
                         LSTM2_SMEM);
    cudaFuncSetAttribute(lstm_mma_kernel<1>, cudaFuncAttributeMaxDynamicSharedMemorySize,
                         LSTM2_SMEM);
    cudaFuncSetAttribute(mma_gemm_kernel, cudaFuncAttributeMaxDynamicSharedMemorySize,
                         GEMM_SMEM);

    dim3 mgrid(32, 256);   // 32 n-tiles (4096/128), 256 m-tiles

    // ---- layer 0 ----
    convert_f16_kernel<<<1024, 256>>>(Wih0, wh0, 2 * G4 * 256);
    convert_f16_kernel<<<2048, 256>>>(input, xh, Mtot * 256);
    mma_gemm_kernel<<<mgrid, 256, GEMM_SMEM>>>(wh0, xh, b0, xwh, 256);
    convert_f16_kernel<<<2048, 256>>>(Wih1, wh1, 2 * G4 * 1024);
    init_kernel<<<64, 256>>>();
    // layer-0 LSTM writes its output straight into xh as [m][dir*512+u] fp16
    lstm_mma_kernel<1><<<NCTA_LSTM, 256, LSTM2_SMEM>>>(xwh, Whh0, nullptr, xh);

    // ---- layer 1 ----
    mma_gemm_kernel<<<mgrid, 256, GEMM_SMEM>>>(wh1, xh, b1, xwh, 1024);
    init_kernel<<<64, 256>>>();
    lstm_mma_kernel<0><<<NCTA_LSTM, 256, LSTM2_SMEM>>>(xwh, Whh1, out1h, nullptr);

    // ---- attention + head ----
    attn_logit_kernel<<<Tn, 512>>>(out1h, Wa, ba, logit);
    softmax_kernel<<<Bn, Tn>>>(logit, outp, aT);
    pool_kernel<<<Hn, 512>>>(out1h, aT, pooledT);
    pred_kernel<<<Bn, NOUT>>>(pooledT, Wo, bo, outp);
}